// round 9
// baseline (speedup 1.0000x reference)
#include <cuda_runtime.h>

#define B_    256
#define N_    8192
#define DK_   128
#define DIN_  512
#define OUTD_ 134
#define NS_   5
#define TILE_ 4096   // elements per k4 block
#define BB_   4      // batches per k1 block
#define KP_   128    // k2 blocks per batch (N/64)

// ---- device scratch ----
__device__ float g_escores[B_ * N_];      // exp(score) (no max shift needed; |score| <~ 6)
__device__ float g_q[B_ * DK_];           // query pre-scaled by 1/sqrt(dk)
__device__ float g_shift[B_ * NS_];       // softmaxed shift distribution
__device__ float g_gate[B_];
__device__ float g_partial[B_ * KP_];     // per-block exp sums (deterministic)

__device__ __forceinline__ float warp_sum(float v) {
#pragma unroll
    for (int o = 16; o; o >>= 1) v += __shfl_xor_sync(0xffffffffu, v, o);
    return v;
}

// ---- K1: head GEMM with 4-batch W reuse; grid (17, 64), 256 threads ----
__global__ void k1_head(const float* __restrict__ inp,
                        const float* __restrict__ W,
                        const float* __restrict__ bias) {
    __shared__ float s_in[BB_][DIN_];
    __shared__ float s_tail[BB_][6];      // args[128..133] per batch (bx==16 only)
    const int tid = threadIdx.x;
    const int warp = tid >> 5, lane = tid & 31;
    const int b0 = blockIdx.y * BB_;

    // load 4 input rows (512 float4, 256 threads -> 2 each), coalesced
    {
        const float4* ip = reinterpret_cast<const float4*>(inp + (size_t)b0 * DIN_);
        float4* sp = &reinterpret_cast<float4(*)[DIN_ / 4]>(s_in)[0][0];
        sp[tid] = ip[tid];
        sp[tid + 256] = ip[tid + 256];
    }
    __syncthreads();

    const int o = blockIdx.x * 8 + warp;
    if (o < OUTD_) {
        const float4* wr = reinterpret_cast<const float4*>(W + (size_t)o * DIN_);
        float4 w[4];
#pragma unroll
        for (int j = 0; j < 4; j++) w[j] = wr[lane + 32 * j];

        float acc[BB_];
#pragma unroll
        for (int bb = 0; bb < BB_; bb++) acc[bb] = 0.f;
#pragma unroll
        for (int j = 0; j < 4; j++) {
#pragma unroll
            for (int bb = 0; bb < BB_; bb++) {
                const float4 x = reinterpret_cast<const float4*>(s_in[bb])[lane + 32 * j];
                acc[bb] = fmaf(w[j].x, x.x,
                           fmaf(w[j].y, x.y,
                            fmaf(w[j].z, x.z,
                             fmaf(w[j].w, x.w, acc[bb]))));
            }
        }
        const float bo = bias[o];
#pragma unroll
        for (int bb = 0; bb < BB_; bb++) {
            float s = warp_sum(acc[bb]);
            if (lane == 0) {
                s += bo;
                if (o < DK_)
                    g_q[(size_t)(b0 + bb) * DK_ + o] = s * 0.088388347648318447f;
                else
                    s_tail[bb][o - DK_] = s;
            }
        }
    }
    if (blockIdx.x == 16) {
        __syncthreads();
        if (tid < BB_) {
            const int b = b0 + tid;
            g_gate[b] = 1.f / (1.f + __expf(-s_tail[tid][0]));
            float mx = s_tail[tid][1];
#pragma unroll
            for (int s = 2; s <= NS_; s++) mx = fmaxf(mx, s_tail[tid][s]);
            float e[NS_], sum = 0.f;
#pragma unroll
            for (int s = 0; s < NS_; s++) { e[s] = __expf(s_tail[tid][1 + s] - mx); sum += e[s]; }
            float inv = 1.f / sum;
#pragma unroll
            for (int s = 0; s < NS_; s++) g_shift[b * NS_ + s] = e[s] * inv;
        }
    }
}

// ---- K2: e = exp(memory[b,n,:] . q[b,:]) ; 8 rows/warp, 64 rows/block (HBM floor) ----
__global__ void k2_scores(const float* __restrict__ mem) {
    __shared__ float s_q[DK_];
    __shared__ float s_ws[8];
    const int b = blockIdx.y, tid = threadIdx.x;
    if (tid < DK_) s_q[tid] = g_q[b * DK_ + tid];
    __syncthreads();
    const int warp = tid >> 5, lane = tid & 31;
    const float4 q4 = reinterpret_cast<float4*>(s_q)[lane];
    const int n0 = blockIdx.x * 64 + warp * 8;
    const float4* mp = reinterpret_cast<const float4*>(mem)
                       + ((size_t)b * N_ + n0) * (DK_ / 4) + lane;
    float4 m[8];
#pragma unroll
    for (int r = 0; r < 8; r++) m[r] = mp[32 * r];
    float d[8];
#pragma unroll
    for (int r = 0; r < 8; r++)
        d[r] = m[r].x * q4.x + m[r].y * q4.y + m[r].z * q4.z + m[r].w * q4.w;
#pragma unroll
    for (int r = 0; r < 8; r++) d[r] = warp_sum(d[r]);
    if (lane == 0) {
        float e[8];
#pragma unroll
        for (int r = 0; r < 8; r++) e[r] = __expf(d[r]);
        float* sc = g_escores + (size_t)b * N_ + n0;
        *reinterpret_cast<float4*>(sc)     = make_float4(e[0], e[1], e[2], e[3]);
        *reinterpret_cast<float4*>(sc + 4) = make_float4(e[4], e[5], e[6], e[7]);
        float t = 0.f;
#pragma unroll
        for (int r = 0; r < 8; r++) t += e[r];
        s_ws[warp] = t;
    }
    __syncthreads();
    if (tid == 0) {
        float t = 0.f;
#pragma unroll
        for (int w = 0; w < 8; w++) t += s_ws[w];
        g_partial[b * KP_ + blockIdx.x] = t;  // fixed order -> deterministic
    }
}

// ---- K4: fused Z-reduce + interp + 5-tap circular shift, 4096 elems/block ----
__global__ void k4_out(const float* __restrict__ prev, float* __restrict__ out) {
    __shared__ float s_int[TILE_ + 8];
    __shared__ float s_sh[NS_];
    __shared__ float s_red[4];
    __shared__ float s_c[2];
    const int b = blockIdx.y, tid = threadIdx.x;
    const int warp = tid >> 5, lane = tid & 31;
    const int base = blockIdx.x * TILE_;

    // deterministic Z reduce over 128 partials (warps 0..3)
    float p = (tid < KP_) ? g_partial[b * KP_ + tid] : 0.f;
    p = warp_sum(p);
    if (lane == 0 && warp < 4) s_red[warp] = p;
    if (tid < NS_) s_sh[tid] = g_shift[b * NS_ + tid];
    __syncthreads();
    if (tid == 0) {
        const float Z = (s_red[0] + s_red[1]) + (s_red[2] + s_red[3]);
        const float g = g_gate[b];
        s_c[0] = g / Z;
        s_c[1] = 1.f - g;
    }
    __syncthreads();
    const float cA = s_c[0], cB = s_c[1];

    const float4* ep = reinterpret_cast<const float4*>(g_escores + (size_t)b * N_ + base);
    const float4* pp = reinterpret_cast<const float4*>(prev + (size_t)b * N_ + base);
#pragma unroll
    for (int i = 0; i < TILE_ / 1024; i++) {
        const int v = tid + i * 256;
        const float4 e = ep[v], pr = pp[v];
        float4 r;
        r.x = cA * e.x + cB * pr.x;
        r.y = cA * e.y + cB * pr.y;
        r.z = cA * e.z + cB * pr.z;
        r.w = cA * e.w + cB * pr.w;
        *reinterpret_cast<float4*>(s_int + 4 + v * 4) = r;
    }
    if (tid < 4) {
        const int k = (tid < 2) ? (tid - 2) : (TILE_ + tid - 2);
        const int n = (base + k + N_) & (N_ - 1);
        const size_t idx = (size_t)b * N_ + n;
        s_int[4 + k] = cA * g_escores[idx] + cB * prev[idx];
    }
    __syncthreads();

    const float sh0 = s_sh[0], sh1 = s_sh[1], sh2 = s_sh[2], sh3 = s_sh[3], sh4 = s_sh[4];
    float4* op = reinterpret_cast<float4*>(out + (size_t)b * N_ + base);
    const float4* si4 = reinterpret_cast<const float4*>(s_int);
#pragma unroll
    for (int i = 0; i < TILE_ / 1024; i++) {
        const int v = tid + i * 256;
        const float4 f0 = si4[v];
        const float4 f1 = si4[v + 1];
        const float4 f2 = si4[v + 2];
        float4 o;
        o.x = sh0 * f0.z + sh1 * f0.w + sh2 * f1.x + sh3 * f1.y + sh4 * f1.z;
        o.y = sh0 * f0.w + sh1 * f1.x + sh2 * f1.y + sh3 * f1.z + sh4 * f1.w;
        o.z = sh0 * f1.x + sh1 * f1.y + sh2 * f1.z + sh3 * f1.w + sh4 * f2.x;
        o.w = sh0 * f1.y + sh1 * f1.z + sh2 * f1.w + sh3 * f2.x + sh4 * f2.y;
        op[v] = o;
    }
}

extern "C" void kernel_launch(void* const* d_in, const int* in_sizes, int n_in,
                              void* d_out, int out_size) {
    const float* inp  = (const float*)d_in[0];
    const float* mem  = (const float*)d_in[1];
    const float* prev = (const float*)d_in[2];
    const float* W    = (const float*)d_in[3];
    const float* bias = (const float*)d_in[4];
    float* out = (float*)d_out;

    k1_head<<<dim3(17, B_ / BB_), 256>>>(inp, W, bias);
    k2_scores<<<dim3(KP_, B_), 256>>>(mem);
    k4_out<<<dim3(N_ / TILE_, B_), 256>>>(prev, out);
}

// round 10
// speedup vs baseline: 1.0243x; 1.0243x over previous
#include <cuda_runtime.h>

#define B_    256
#define N_    8192
#define DK_   128
#define DIN_  512
#define OUTD_ 134
#define NS_   5
#define TILE_ 2048   // elements per k4 block
#define BB_   8      // batches per k1 block
#define KP_   1024   // per-warp partials per batch (128 blocks x 8 warps)

// ---- device scratch ----
__device__ float g_escores[B_ * N_];      // exp(score) (no max shift needed; |score| <~ 6)
__device__ float g_q[B_ * DK_];           // query pre-scaled by 1/sqrt(dk)
__device__ float g_shift[B_ * NS_];       // softmaxed shift distribution
__device__ float g_gate[B_];
__device__ float g_partial[B_ * KP_];     // per-warp exp sums (deterministic)

__device__ __forceinline__ float warp_sum(float v) {
#pragma unroll
    for (int o = 16; o; o >>= 1) v += __shfl_xor_sync(0xffffffffu, v, o);
    return v;
}

// ---- K1: head GEMM with 8-batch W reuse; grid (17, 32), 256 threads (R8 shape) ----
__global__ void k1_head(const float* __restrict__ inp,
                        const float* __restrict__ W,
                        const float* __restrict__ bias) {
    __shared__ float s_in[BB_][DIN_];
    __shared__ float s_tail[BB_][6];
    const int tid = threadIdx.x;
    const int warp = tid >> 5, lane = tid & 31;
    const int b0 = blockIdx.y * BB_;

    {
        const float4* ip = reinterpret_cast<const float4*>(inp + (size_t)b0 * DIN_);
        float4* sp = &reinterpret_cast<float4(*)[DIN_ / 4]>(s_in)[0][0];
#pragma unroll
        for (int i = 0; i < 4; i++) sp[tid + i * 256] = ip[tid + i * 256];
    }
    __syncthreads();

    const int o = blockIdx.x * 8 + warp;
    if (o < OUTD_) {
        const float4* wr = reinterpret_cast<const float4*>(W + (size_t)o * DIN_);
        float4 w[4];
#pragma unroll
        for (int j = 0; j < 4; j++) w[j] = wr[lane + 32 * j];

        float acc[BB_];
#pragma unroll
        for (int bb = 0; bb < BB_; bb++) acc[bb] = 0.f;
#pragma unroll
        for (int j = 0; j < 4; j++) {
#pragma unroll
            for (int bb = 0; bb < BB_; bb++) {
                const float4 x = reinterpret_cast<const float4*>(s_in[bb])[lane + 32 * j];
                acc[bb] = fmaf(w[j].x, x.x,
                           fmaf(w[j].y, x.y,
                            fmaf(w[j].z, x.z,
                             fmaf(w[j].w, x.w, acc[bb]))));
            }
        }
        const float bo = bias[o];
#pragma unroll
        for (int bb = 0; bb < BB_; bb++) {
            float s = warp_sum(acc[bb]);
            if (lane == 0) {
                s += bo;
                if (o < DK_)
                    g_q[(size_t)(b0 + bb) * DK_ + o] = s * 0.088388347648318447f;
                else
                    s_tail[bb][o - DK_] = s;
            }
        }
    }
    if (blockIdx.x == 16) {
        __syncthreads();
        if (tid < BB_) {
            const int b = b0 + tid;
            g_gate[b] = 1.f / (1.f + __expf(-s_tail[tid][0]));
            float mx = s_tail[tid][1];
#pragma unroll
            for (int s = 2; s <= NS_; s++) mx = fmaxf(mx, s_tail[tid][s]);
            float e[NS_], sum = 0.f;
#pragma unroll
            for (int s = 0; s < NS_; s++) { e[s] = __expf(s_tail[tid][1 + s] - mx); sum += e[s]; }
            float inv = 1.f / sum;
#pragma unroll
            for (int s = 0; s < NS_; s++) g_shift[b * NS_ + s] = e[s] * inv;
        }
    }
}

// ---- K2: no smem, no barrier; PDL overlap with k1 tail ----
// 8 rows/warp. Memory-row loads (independent of k1) issue BEFORE the grid
// dependency sync; q is read per-lane via LDG.128 after.
__global__ void k2_scores(const float* __restrict__ mem) {
    const int b = blockIdx.y, tid = threadIdx.x;
    const int warp = tid >> 5, lane = tid & 31;
    const int n0 = blockIdx.x * 64 + warp * 8;
    const float4* mp = reinterpret_cast<const float4*>(mem)
                       + ((size_t)b * N_ + n0) * (DK_ / 4) + lane;
    float4 m[8];
#pragma unroll
    for (int r = 0; r < 8; r++) m[r] = mp[32 * r];

    cudaGridDependencySynchronize();   // wait for k1's g_q

    const float4 q4 = *reinterpret_cast<const float4*>(g_q + (size_t)b * DK_ + lane * 4);
    float d[8];
#pragma unroll
    for (int r = 0; r < 8; r++)
        d[r] = m[r].x * q4.x + m[r].y * q4.y + m[r].z * q4.z + m[r].w * q4.w;
#pragma unroll
    for (int r = 0; r < 8; r++) d[r] = warp_sum(d[r]);
    if (lane == 0) {
        float e[8];
#pragma unroll
        for (int r = 0; r < 8; r++) e[r] = __expf(d[r]);
        float* sc = g_escores + (size_t)b * N_ + n0;
        *reinterpret_cast<float4*>(sc)     = make_float4(e[0], e[1], e[2], e[3]);
        *reinterpret_cast<float4*>(sc + 4) = make_float4(e[4], e[5], e[6], e[7]);
        float t = 0.f;
#pragma unroll
        for (int r = 0; r < 8; r++) t += e[r];
        g_partial[b * KP_ + blockIdx.x * 8 + warp] = t;  // fixed slot -> deterministic
    }
}

// ---- K4: fused Z-reduce + interp + 5-tap circular shift, 2048 elems/block ----
// prev loads issue before the dependency sync on k2.
__global__ void k4_out(const float* __restrict__ prev, float* __restrict__ out) {
    __shared__ float s_int[TILE_ + 8];
    __shared__ float s_sh[NS_];
    __shared__ float s_red[8];
    __shared__ float s_c[2];
    const int b = blockIdx.y, tid = threadIdx.x;
    const int warp = tid >> 5, lane = tid & 31;
    const int base = blockIdx.x * TILE_;

    // independent of k2: prev body + halo
    const float4* pp = reinterpret_cast<const float4*>(prev + (size_t)b * N_ + base);
    float4 pr[TILE_ / 1024];
#pragma unroll
    for (int i = 0; i < TILE_ / 1024; i++) pr[i] = pp[tid + i * 256];
    float pr_halo = 0.f;
    int hk = 0;
    if (tid < 4) {
        hk = (tid < 2) ? (tid - 2) : (TILE_ + tid - 2);
        pr_halo = prev[(size_t)b * N_ + ((base + hk + N_) & (N_ - 1))];
    }

    cudaGridDependencySynchronize();   // wait for k2's escores + partials

    // deterministic Z reduce over 1024 per-warp partials
    float p = 0.f;
    const float* gp = g_partial + (size_t)b * KP_;
#pragma unroll
    for (int i = 0; i < 4; i++) p += gp[tid + i * 256];
    p = warp_sum(p);
    if (lane == 0) s_red[warp] = p;
    if (tid < NS_) s_sh[tid] = g_shift[b * NS_ + tid];
    __syncthreads();
    if (tid == 0) {
        float Z = 0.f;
#pragma unroll
        for (int w = 0; w < 8; w++) Z += s_red[w];
        const float g = g_gate[b];
        s_c[0] = g / Z;
        s_c[1] = 1.f - g;
    }
    __syncthreads();
    const float cA = s_c[0], cB = s_c[1];

    const float4* ep = reinterpret_cast<const float4*>(g_escores + (size_t)b * N_ + base);
#pragma unroll
    for (int i = 0; i < TILE_ / 1024; i++) {
        const int v = tid + i * 256;
        const float4 e = ep[v];
        float4 r;
        r.x = cA * e.x + cB * pr[i].x;
        r.y = cA * e.y + cB * pr[i].y;
        r.z = cA * e.z + cB * pr[i].z;
        r.w = cA * e.w + cB * pr[i].w;
        *reinterpret_cast<float4*>(s_int + 4 + v * 4) = r;
    }
    if (tid < 4) {
        const int n = (base + hk + N_) & (N_ - 1);
        s_int[4 + hk] = cA * g_escores[(size_t)b * N_ + n] + cB * pr_halo;
    }
    __syncthreads();

    const float sh0 = s_sh[0], sh1 = s_sh[1], sh2 = s_sh[2], sh3 = s_sh[3], sh4 = s_sh[4];
    float4* op = reinterpret_cast<float4*>(out + (size_t)b * N_ + base);
    const float4* si4 = reinterpret_cast<const float4*>(s_int);
#pragma unroll
    for (int i = 0; i < TILE_ / 1024; i++) {
        const int v = tid + i * 256;
        const float4 f0 = si4[v];
        const float4 f1 = si4[v + 1];
        const float4 f2 = si4[v + 2];
        float4 o;
        o.x = sh0 * f0.z + sh1 * f0.w + sh2 * f1.x + sh3 * f1.y + sh4 * f1.z;
        o.y = sh0 * f0.w + sh1 * f1.x + sh2 * f1.y + sh3 * f1.z + sh4 * f1.w;
        o.z = sh0 * f1.x + sh1 * f1.y + sh2 * f1.z + sh3 * f1.w + sh4 * f2.x;
        o.w = sh0 * f1.y + sh1 * f1.z + sh2 * f1.w + sh3 * f2.x + sh4 * f2.y;
        op[v] = o;
    }
}

extern "C" void kernel_launch(void* const* d_in, const int* in_sizes, int n_in,
                              void* d_out, int out_size) {
    const float* inp  = (const float*)d_in[0];
    const float* mem  = (const float*)d_in[1];
    const float* prev = (const float*)d_in[2];
    const float* W    = (const float*)d_in[3];
    const float* bias = (const float*)d_in[4];
    float* out = (float*)d_out;

    k1_head<<<dim3(17, B_ / BB_), 256>>>(inp, W, bias);

    cudaLaunchAttribute attrs[1];
    attrs[0].id = cudaLaunchAttributeProgrammaticStreamSerialization;
    attrs[0].val.programmaticStreamSerializationAllowed = 1;

    {
        cudaLaunchConfig_t cfg = {};
        cfg.gridDim = dim3(N_ / 64, B_);
        cfg.blockDim = dim3(256, 1, 1);
        cfg.attrs = attrs;
        cfg.numAttrs = 1;
        cudaLaunchKernelEx(&cfg, k2_scores, mem);
    }
    {
        cudaLaunchConfig_t cfg = {};
        cfg.gridDim = dim3(N_ / TILE_, B_);
        cfg.blockDim = dim3(256, 1, 1);
        cfg.attrs = attrs;
        cfg.numAttrs = 1;
        cudaLaunchKernelEx(&cfg, k4_out, prev, out);
    }
}

// round 11
// speedup vs baseline: 1.0477x; 1.0229x over previous
#include <cuda_runtime.h>

#define B_    256
#define N_    8192
#define DK_   128
#define DIN_  512
#define OUTD_ 134
#define NS_   5
#define TILE_ 2048   // elements per k4 block
#define BB_   8      // batches per k1 block
#define KP_   1024   // per-warp partials per batch (128 blocks x 8 warps)

// ---- device scratch ----
__device__ float g_escores[B_ * N_];      // exp(score) (no max shift needed; |score| <~ 6)
__device__ float g_q[B_ * DK_];           // query pre-scaled by 1/sqrt(dk)
__device__ float g_shift[B_ * NS_];       // softmaxed shift distribution
__device__ float g_gate[B_];
__device__ float g_partial[B_ * KP_];     // per-warp exp sums (deterministic)

__device__ __forceinline__ float warp_sum(float v) {
#pragma unroll
    for (int o = 16; o; o >>= 1) v += __shfl_xor_sync(0xffffffffu, v, o);
    return v;
}

// ---- K1: head GEMM with 8-batch W reuse; grid (17, 32), 256 threads ----
__global__ void k1_head(const float* __restrict__ inp,
                        const float* __restrict__ W,
                        const float* __restrict__ bias) {
    __shared__ float s_in[BB_][DIN_];
    __shared__ float s_tail[BB_][6];
    const int tid = threadIdx.x;
    const int warp = tid >> 5, lane = tid & 31;
    const int b0 = blockIdx.y * BB_;

    {
        const float4* ip = reinterpret_cast<const float4*>(inp + (size_t)b0 * DIN_);
        float4* sp = &reinterpret_cast<float4(*)[DIN_ / 4]>(s_in)[0][0];
#pragma unroll
        for (int i = 0; i < 4; i++) sp[tid + i * 256] = ip[tid + i * 256];
    }
    __syncthreads();

    const int o = blockIdx.x * 8 + warp;
    if (o < OUTD_) {
        const float4* wr = reinterpret_cast<const float4*>(W + (size_t)o * DIN_);
        float4 w[4];
#pragma unroll
        for (int j = 0; j < 4; j++) w[j] = wr[lane + 32 * j];

        float acc[BB_];
#pragma unroll
        for (int bb = 0; bb < BB_; bb++) acc[bb] = 0.f;
#pragma unroll
        for (int j = 0; j < 4; j++) {
#pragma unroll
            for (int bb = 0; bb < BB_; bb++) {
                const float4 x = reinterpret_cast<const float4*>(s_in[bb])[lane + 32 * j];
                acc[bb] = fmaf(w[j].x, x.x,
                           fmaf(w[j].y, x.y,
                            fmaf(w[j].z, x.z,
                             fmaf(w[j].w, x.w, acc[bb]))));
            }
        }
        const float bo = bias[o];
#pragma unroll
        for (int bb = 0; bb < BB_; bb++) {
            float s = warp_sum(acc[bb]);
            if (lane == 0) {
                s += bo;
                if (o < DK_)
                    g_q[(size_t)(b0 + bb) * DK_ + o] = s * 0.088388347648318447f;
                else
                    s_tail[bb][o - DK_] = s;
            }
        }
    }
    if (blockIdx.x == 16) {
        __syncthreads();
        if (tid < BB_) {
            const int b = b0 + tid;
            g_gate[b] = 1.f / (1.f + __expf(-s_tail[tid][0]));
            float mx = s_tail[tid][1];
#pragma unroll
            for (int s = 2; s <= NS_; s++) mx = fmaxf(mx, s_tail[tid][s]);
            float e[NS_], sum = 0.f;
#pragma unroll
            for (int s = 0; s < NS_; s++) { e[s] = __expf(s_tail[tid][1 + s] - mx); sum += e[s]; }
            float inv = 1.f / sum;
#pragma unroll
            for (int s = 0; s < NS_; s++) g_shift[b * NS_ + s] = e[s] * inv;
        }
    }
}

// ---- K2: streaming (evict-first) reads of memory; PDL overlap with k1 tail ----
__global__ void k2_scores(const float* __restrict__ mem) {
    const int b = blockIdx.y, tid = threadIdx.x;
    const int warp = tid >> 5, lane = tid & 31;
    const int n0 = blockIdx.x * 64 + warp * 8;
    const float4* mp = reinterpret_cast<const float4*>(mem)
                       + ((size_t)b * N_ + n0) * (DK_ / 4) + lane;
    float4 m[8];
#pragma unroll
    for (int r = 0; r < 8; r++) m[r] = __ldcs(mp + 32 * r);   // evict-first: don't thrash L2

    cudaGridDependencySynchronize();   // wait for k1's g_q

    const float4 q4 = *reinterpret_cast<const float4*>(g_q + (size_t)b * DK_ + lane * 4);
    float d[8];
#pragma unroll
    for (int r = 0; r < 8; r++)
        d[r] = m[r].x * q4.x + m[r].y * q4.y + m[r].z * q4.z + m[r].w * q4.w;
#pragma unroll
    for (int r = 0; r < 8; r++) d[r] = warp_sum(d[r]);
    if (lane == 0) {
        float e[8];
#pragma unroll
        for (int r = 0; r < 8; r++) e[r] = __expf(d[r]);
        float* sc = g_escores + (size_t)b * N_ + n0;
        *reinterpret_cast<float4*>(sc)     = make_float4(e[0], e[1], e[2], e[3]);
        *reinterpret_cast<float4*>(sc + 4) = make_float4(e[4], e[5], e[6], e[7]);
        float t = 0.f;
#pragma unroll
        for (int r = 0; r < 8; r++) t += e[r];
        g_partial[b * KP_ + blockIdx.x * 8 + warp] = t;  // fixed slot -> deterministic
    }
}

// ---- K4: fused Z-reduce + interp + 5-tap circular shift, 2048 elems/block ----
__global__ void k4_out(const float* __restrict__ prev, float* __restrict__ out) {
    __shared__ float s_int[TILE_ + 8];
    __shared__ float s_sh[NS_];
    __shared__ float s_red[8];
    __shared__ float s_c[2];
    const int b = blockIdx.y, tid = threadIdx.x;
    const int warp = tid >> 5, lane = tid & 31;
    const int base = blockIdx.x * TILE_;

    // independent of k2: prev body + halo (read-once -> evict-first)
    const float4* pp = reinterpret_cast<const float4*>(prev + (size_t)b * N_ + base);
    float4 pr[TILE_ / 1024];
#pragma unroll
    for (int i = 0; i < TILE_ / 1024; i++) pr[i] = __ldcs(pp + tid + i * 256);
    float pr_halo = 0.f;
    int hk = 0;
    if (tid < 4) {
        hk = (tid < 2) ? (tid - 2) : (TILE_ + tid - 2);
        pr_halo = prev[(size_t)b * N_ + ((base + hk + N_) & (N_ - 1))];
    }

    cudaGridDependencySynchronize();   // wait for k2's escores + partials

    // deterministic Z reduce over 1024 per-warp partials
    float p = 0.f;
    const float* gp = g_partial + (size_t)b * KP_;
#pragma unroll
    for (int i = 0; i < 4; i++) p += gp[tid + i * 256];
    p = warp_sum(p);
    if (lane == 0) s_red[warp] = p;
    if (tid < NS_) s_sh[tid] = g_shift[b * NS_ + tid];
    __syncthreads();
    if (tid == 0) {
        float Z = 0.f;
#pragma unroll
        for (int w = 0; w < 8; w++) Z += s_red[w];
        const float g = g_gate[b];
        s_c[0] = g / Z;
        s_c[1] = 1.f - g;
    }
    __syncthreads();
    const float cA = s_c[0], cB = s_c[1];

    const float4* ep = reinterpret_cast<const float4*>(g_escores + (size_t)b * N_ + base);
#pragma unroll
    for (int i = 0; i < TILE_ / 1024; i++) {
        const int v = tid + i * 256;
        const float4 e = __ldcs(ep + v);     // last read of escores
        float4 r;
        r.x = cA * e.x + cB * pr[i].x;
        r.y = cA * e.y + cB * pr[i].y;
        r.z = cA * e.z + cB * pr[i].z;
        r.w = cA * e.w + cB * pr[i].w;
        *reinterpret_cast<float4*>(s_int + 4 + v * 4) = r;
    }
    if (tid < 4) {
        const int n = (base + hk + N_) & (N_ - 1);
        s_int[4 + hk] = cA * g_escores[(size_t)b * N_ + n] + cB * pr_halo;
    }
    __syncthreads();

    const float sh0 = s_sh[0], sh1 = s_sh[1], sh2 = s_sh[2], sh3 = s_sh[3], sh4 = s_sh[4];
    float4* op = reinterpret_cast<float4*>(out + (size_t)b * N_ + base);
    const float4* si4 = reinterpret_cast<const float4*>(s_int);
#pragma unroll
    for (int i = 0; i < TILE_ / 1024; i++) {
        const int v = tid + i * 256;
        const float4 f0 = si4[v];
        const float4 f1 = si4[v + 1];
        const float4 f2 = si4[v + 2];
        float4 o;
        o.x = sh0 * f0.z + sh1 * f0.w + sh2 * f1.x + sh3 * f1.y + sh4 * f1.z;
        o.y = sh0 * f0.w + sh1 * f1.x + sh2 * f1.y + sh3 * f1.z + sh4 * f1.w;
        o.z = sh0 * f1.x + sh1 * f1.y + sh2 * f1.z + sh3 * f1.w + sh4 * f2.x;
        o.w = sh0 * f1.y + sh1 * f1.z + sh2 * f1.w + sh3 * f2.x + sh4 * f2.y;
        __stcs(op + v, o);                   // write-once output, don't pollute L2
    }
}

extern "C" void kernel_launch(void* const* d_in, const int* in_sizes, int n_in,
                              void* d_out, int out_size) {
    const float* inp  = (const float*)d_in[0];
    const float* mem  = (const float*)d_in[1];
    const float* prev = (const float*)d_in[2];
    const float* W    = (const float*)d_in[3];
    const float* bias = (const float*)d_in[4];
    float* out = (float*)d_out;

    k1_head<<<dim3(17, B_ / BB_), 256>>>(inp, W, bias);

    cudaLaunchAttribute attrs[1];
    attrs[0].id = cudaLaunchAttributeProgrammaticStreamSerialization;
    attrs[0].val.programmaticStreamSerializationAllowed = 1;

    {
        cudaLaunchConfig_t cfg = {};
        cfg.gridDim = dim3(N_ / 64, B_);
        cfg.blockDim = dim3(256, 1, 1);
        cfg.attrs = attrs;
        cfg.numAttrs = 1;
        cudaLaunchKernelEx(&cfg, k2_scores, mem);
    }
    {
        cudaLaunchConfig_t cfg = {};
        cfg.gridDim = dim3(N_ / TILE_, B_);
        cfg.blockDim = dim3(256, 1, 1);
        cfg.attrs = attrs;
        cfg.numAttrs = 1;
        cudaLaunchKernelEx(&cfg, k4_out, prev, out);
    }
}